// round 1
// baseline (speedup 1.0000x reference)
#include <cuda_runtime.h>
#include <mma.h>

using namespace nvcuda;

// ---------------- problem constants ----------------
constexpr int B_  = 8;
constexpr int T_  = 513;
constexpr int L_  = 512;   // T-1
constexpr int M_  = 8;
constexpr int D_  = 512;
constexpr int H_  = 8;
constexpr int DH_ = 64;
constexpr int O_  = 64;
constexpr int SS_ = 72;    // M + O

constexpr int NTT = B_ * L_ * M_;   // 32768 temporal rows
constexpr int NSS = B_ * SS_;       // 576 ss rows

constexpr long long SZ_TOUT = (long long)B_ * T_ * M_ * D_;        // 16,809,984
constexpr long long SZ_OOUT = (long long)B_ * O_ * D_;             // 262,144
constexpr long long SZ_TATT = (long long)B_ * H_ * L_ * M_ * SS_;  // 18,874,368
constexpr long long OFF_OOUT = SZ_TOUT;
constexpr long long OFF_TATT = OFF_OOUT + SZ_OOUT;
constexpr long long OFF_OATT = OFF_TATT + SZ_TATT;

// ---------------- scratch (static device globals; no allocs) ----------------
__device__ float g_tt[3][(size_t)NTT * D_];   // Qtt, Ktt, Vtt (no bias)
__device__ float g_ss[3][(size_t)NSS * D_];   // Qss, Kss, Vss (no bias); Kts/Vts = rows 8..71

// ============================================================================
// Projection GEMM: C[r,n] = sum_d X[r,d] * W[n,d]   (bias added later, on load)
// tf32 WMMA, 128x128 C tile, BK=16, 8 warps (2x4), each warp 64x32 (4x2 frags).
// MODE 0: temporal rows (gathered from temporal_concat[:,1:]), 32768 rows.
// MODE 1: ss rows (concat of temporal_concat[:,0] and others_concat), 576 rows.
// ============================================================================
template<int MODE>
__global__ void proj_gemm(const float* __restrict__ Xt, const float* __restrict__ Xo,
                          const float* __restrict__ Wq, const float* __restrict__ Wk,
                          const float* __restrict__ Wv)
{
    constexpr int BM = 128, BN = 128, BK = 16, LDS = BK + 4;
    __shared__ float As[BM * LDS];
    __shared__ float Bs[BN * LDS];

    const int tid  = threadIdx.x;
    const int warp = tid >> 5;
    const int wr   = warp >> 2;   // 0..1
    const int wc   = warp & 3;    // 0..3
    const int tm   = blockIdx.x;
    const int tn   = blockIdx.y;
    const int mat  = blockIdx.z;

    const float* W   = (mat == 0) ? Wq : ((mat == 1) ? Wk : Wv);
    float*       Out = (MODE == 0) ? g_tt[mat] : g_ss[mat];
    const int  Mrows = (MODE == 0) ? NTT : NSS;

    wmma::fragment<wmma::accumulator, 16, 16, 8, float> acc[4][2];
#pragma unroll
    for (int i = 0; i < 4; i++)
#pragma unroll
        for (int j = 0; j < 2; j++) wmma::fill_fragment(acc[i][j], 0.0f);

    for (int k0 = 0; k0 < D_; k0 += BK) {
#pragma unroll
        for (int it = 0; it < 2; it++) {
            int f   = tid + it * 256;   // 0..511 -> 512 float4s per operand
            int row = f >> 2;           // 0..127
            int col = (f & 3) * 4;      // 0,4,8,12
            // ---- A (gathered X rows) ----
            float4 v = make_float4(0.f, 0.f, 0.f, 0.f);
            int gr = tm * BM + row;
            const float* src = nullptr;
            if (MODE == 0) {
                // temporal_concat[b, 1+l, m, :] ; r = b*4096 + l*8 + m
                src = Xt + (size_t)(gr + ((gr >> 12) << 3) + 8) * D_;
            } else {
                if (gr < NSS) {
                    int bb = gr / SS_;
                    int jj = gr - bb * SS_;
                    src = (jj < M_) ? (Xt + (size_t)(bb * 4104 + jj) * D_)
                                    : (Xo + (size_t)(bb * O_ + jj - M_) * D_);
                }
            }
            if (src) v = *reinterpret_cast<const float4*>(src + k0 + col);
            *reinterpret_cast<float4*>(&As[row * LDS + col]) = v;
            // ---- B (W rows, K-contiguous) ----
            float4 w = *reinterpret_cast<const float4*>(W + (size_t)(tn * BN + row) * D_ + k0 + col);
            *reinterpret_cast<float4*>(&Bs[row * LDS + col]) = w;
        }
        __syncthreads();

#pragma unroll
        for (int kk = 0; kk < BK; kk += 8) {
            wmma::fragment<wmma::matrix_a, 16, 16, 8, wmma::precision::tf32, wmma::row_major> af[4];
            wmma::fragment<wmma::matrix_b, 16, 16, 8, wmma::precision::tf32, wmma::col_major> bf[2];
#pragma unroll
            for (int i = 0; i < 4; i++) {
                wmma::load_matrix_sync(af[i], &As[(wr * 64 + i * 16) * LDS + kk], LDS);
#pragma unroll
                for (int e = 0; e < af[i].num_elements; e++)
                    af[i].x[e] = wmma::__float_to_tf32(af[i].x[e]);
            }
#pragma unroll
            for (int j = 0; j < 2; j++) {
                wmma::load_matrix_sync(bf[j], &Bs[(wc * 32 + j * 16) * LDS + kk], LDS);
#pragma unroll
                for (int e = 0; e < bf[j].num_elements; e++)
                    bf[j].x[e] = wmma::__float_to_tf32(bf[j].x[e]);
            }
#pragma unroll
            for (int i = 0; i < 4; i++)
#pragma unroll
                for (int j = 0; j < 2; j++)
                    wmma::mma_sync(acc[i][j], af[i], bf[j], acc[i][j]);
        }
        __syncthreads();
    }

#pragma unroll
    for (int i = 0; i < 4; i++) {
        int row0 = tm * BM + wr * 64 + i * 16;
        if (row0 + 16 <= Mrows) {   // Mrows is a multiple of 16 in both modes
#pragma unroll
            for (int j = 0; j < 2; j++)
                wmma::store_matrix_sync(Out + (size_t)row0 * D_ + tn * BN + wc * 32 + j * 16,
                                        acc[i][j], D_, wmma::mem_row_major);
        }
    }
}

// ============================================================================
// Temporal attention. Block = (b, h, chunk of 64 l's). 256 threads.
// Kts/Vts (64x64) staged once per block; per l: 8x64 Q/K/V, S(8x72), softmax,
// out(8x64). Writes temporal_attn and temporal_out[:, 1: ,...].
// ============================================================================
__global__ void temporal_attn_kernel(const float* __restrict__ bq, const float* __restrict__ bk,
                                     const float* __restrict__ bv, float* __restrict__ out)
{
    __shared__ float Kts[64][65];
    __shared__ float Vts[64][65];
    __shared__ float Qs[8][65], Ks[8][65], Vs[8][65];
    __shared__ float S[8][73];
    __shared__ float bq_s[64], bk_s[64], bv_s[64];

    const int tid = threadIdx.x;
    const int b = blockIdx.z, h = blockIdx.y;
    const int l0 = blockIdx.x * 64;
    const int cb = h * DH_;

    if (tid < 64) {
        bq_s[tid] = bq[cb + tid];
        bk_s[tid] = bk[cb + tid];
        bv_s[tid] = bv[cb + tid];
    }
    __syncthreads();

    for (int idx = tid; idx < 64 * 64; idx += 256) {
        int o = idx >> 6, d = idx & 63;
        size_t srow = (size_t)(b * SS_ + 8 + o) * D_ + cb + d;
        Kts[o][d] = g_ss[1][srow] + bk_s[d];
        Vts[o][d] = g_ss[2][srow] + bv_s[d];
    }
    __syncthreads();

    for (int li = 0; li < 64; li++) {
        const int l = l0 + li;
        const size_t rb = (size_t)(b * 4096 + l * 8);

        // load this l's Q,K,V (8x64 each), bias added
#pragma unroll
        for (int it = 0; it < 2; it++) {
            int idx = tid + it * 256;
            int m = idx >> 6, d = idx & 63;
            size_t off = (rb + m) * D_ + cb + d;
            Qs[m][d] = g_tt[0][off] + bq_s[d];
            Ks[m][d] = g_tt[1][off] + bk_s[d];
            Vs[m][d] = g_tt[2][off] + bv_s[d];
        }
        __syncthreads();

        // logits S[m][k], k<8 self-keys, k>=8 others-keys
        for (int e = tid; e < 8 * 72; e += 256) {
            int m = e / 72, k = e - m * 72;
            const float* qrow = Qs[m];
            const float* krow = (k < 8) ? Ks[k] : Kts[k - 8];
            float acc = 0.f;
#pragma unroll
            for (int d = 0; d < 64; d++) acc = fmaf(qrow[d], krow[d], acc);
            S[m][k] = acc * 0.125f;
        }
        __syncthreads();

        // softmax: warp w handles row m=w
        {
            int m = tid >> 5, lane = tid & 31;
            float v0 = S[m][lane];
            float v1 = S[m][lane + 32];
            float v2 = (lane < 8) ? S[m][lane + 64] : -3.4e38f;
            float mx = fmaxf(fmaxf(v0, v1), v2);
#pragma unroll
            for (int s = 16; s; s >>= 1) mx = fmaxf(mx, __shfl_xor_sync(0xffffffffu, mx, s));
            float e0 = __expf(v0 - mx), e1 = __expf(v1 - mx);
            float e2 = (lane < 8) ? __expf(v2 - mx) : 0.f;
            float sm = e0 + e1 + e2;
#pragma unroll
            for (int s = 16; s; s >>= 1) sm += __shfl_xor_sync(0xffffffffu, sm, s);
            float inv = 1.0f / sm;
            float p0 = e0 * inv, p1 = e1 * inv;
            S[m][lane] = p0;
            S[m][lane + 32] = p1;
            size_t abase = OFF_TATT + (((size_t)(b * 8 + h) * 512 + l) * 8 + m) * 72;
            out[abase + lane]      = p0;
            out[abase + lane + 32] = p1;
            if (lane < 8) {
                float p2 = e2 * inv;
                S[m][lane + 64] = p2;
                out[abase + lane + 64] = p2;
            }
        }
        __syncthreads();

        // out[m][d] = sum_n P[m][n] V[n][d] + sum_o P[m][8+o] Vts[o][d]
        for (int e = tid; e < 512; e += 256) {
            int m = e >> 6, d = e & 63;
            float acc = 0.f;
#pragma unroll
            for (int n = 0; n < 8; n++) acc = fmaf(S[m][n], Vs[n][d], acc);
#pragma unroll
            for (int o = 0; o < 64; o++) acc = fmaf(S[m][8 + o], Vts[o][d], acc);
            out[(size_t)(b * 4104 + (1 + l) * 8 + m) * D_ + cb + d] = acc;
        }
        __syncthreads();
    }
}

// ============================================================================
// Others attention. Block = (m-chunk of 24, h, b). 256 threads.
// out scatter follows others.reshape(B,-1,D): p = h*4608 + n*64 + d;
// j = p>>9 -> rows j<8 go to temporal_out[:,0], rows 8..71 to others_out.
// ============================================================================
__global__ void others_attn_kernel(const float* __restrict__ bq, const float* __restrict__ bk,
                                   const float* __restrict__ bv, float* __restrict__ out)
{
    __shared__ float Qc[24][65];
    __shared__ float KV[72][65];
    __shared__ float S[24][73];
    __shared__ float bq_s[64], bk_s[64], bv_s[64];

    const int tid = threadIdx.x;
    const int m0 = blockIdx.x * 24;
    const int h = blockIdx.y, b = blockIdx.z;
    const int cb = h * DH_;

    if (tid < 64) {
        bq_s[tid] = bq[cb + tid];
        bk_s[tid] = bk[cb + tid];
        bv_s[tid] = bv[cb + tid];
    }
    __syncthreads();

    for (int idx = tid; idx < 72 * 64; idx += 256) {
        int n = idx >> 6, d = idx & 63;
        KV[n][d] = g_ss[1][(size_t)(b * SS_ + n) * D_ + cb + d] + bk_s[d];
    }
    for (int idx = tid; idx < 24 * 64; idx += 256) {
        int i = idx >> 6, d = idx & 63;
        Qc[i][d] = g_ss[0][(size_t)(b * SS_ + m0 + i) * D_ + cb + d] + bq_s[d];
    }
    __syncthreads();

    for (int e = tid; e < 24 * 72; e += 256) {
        int i = e / 72, n = e - i * 72;
        float acc = 0.f;
#pragma unroll
        for (int d = 0; d < 64; d++) acc = fmaf(Qc[i][d], KV[n][d], acc);
        S[i][n] = acc * 0.125f;
    }
    __syncthreads();

    {   // softmax: 24 rows over 8 warps
        int w = tid >> 5, lane = tid & 31;
        for (int i = w; i < 24; i += 8) {
            float v0 = S[i][lane];
            float v1 = S[i][lane + 32];
            float v2 = (lane < 8) ? S[i][lane + 64] : -3.4e38f;
            float mx = fmaxf(fmaxf(v0, v1), v2);
#pragma unroll
            for (int s = 16; s; s >>= 1) mx = fmaxf(mx, __shfl_xor_sync(0xffffffffu, mx, s));
            float e0 = __expf(v0 - mx), e1 = __expf(v1 - mx);
            float e2 = (lane < 8) ? __expf(v2 - mx) : 0.f;
            float sm = e0 + e1 + e2;
#pragma unroll
            for (int s = 16; s; s >>= 1) sm += __shfl_xor_sync(0xffffffffu, sm, s);
            float inv = 1.0f / sm;
            size_t abase = OFF_OATT + ((size_t)(b * 8 + h) * 72 + (m0 + i)) * 72;
            float p0 = e0 * inv, p1 = e1 * inv;
            S[i][lane] = p0;       out[abase + lane]      = p0;
            S[i][lane + 32] = p1;  out[abase + lane + 32] = p1;
            if (lane < 8) {
                float p2 = e2 * inv;
                S[i][lane + 64] = p2;
                out[abase + lane + 64] = p2;
            }
        }
    }
    __syncthreads();

    // reload KV with V (+bv)
    for (int idx = tid; idx < 72 * 64; idx += 256) {
        int n = idx >> 6, d = idx & 63;
        KV[n][d] = g_ss[2][(size_t)(b * SS_ + n) * D_ + cb + d] + bv_s[d];
    }
    __syncthreads();

    for (int e = tid; e < 24 * 64; e += 256) {
        int i = e >> 6, d = e & 63;
        float acc = 0.f;
#pragma unroll
        for (int n = 0; n < 72; n++) acc = fmaf(S[i][n], KV[n][d], acc);
        int ng = m0 + i;
        int p = h * 4608 + ng * 64 + d;      // linear within batch of others.reshape(B,-1,D)
        int j = p >> 9;
        int c = p & 511;
        if (j < 8)
            out[(size_t)(b * 4104 + j) * D_ + c] = acc;                       // temporal_out[b,0,j,c]
        else
            out[OFF_OOUT + (size_t)(b * 64 + (j - 8)) * D_ + c] = acc;        // others_out[b,j-8,c]
    }
}

// ============================================================================
extern "C" void kernel_launch(void* const* d_in, const int* in_sizes, int n_in,
                              void* d_out, int out_size)
{
    const float* Xt = (const float*)d_in[0];  // temporal_concat (B,513,M,D)
    const float* Xo = (const float*)d_in[1];  // others_concat   (B,O,D)
    const float* Wq = (const float*)d_in[2];
    const float* bq = (const float*)d_in[3];
    const float* Wk = (const float*)d_in[4];
    const float* bk = (const float*)d_in[5];
    const float* Wv = (const float*)d_in[6];
    const float* bv = (const float*)d_in[7];
    float* out = (float*)d_out;

    proj_gemm<0><<<dim3(NTT / 128, D_ / 128, 3), 256>>>(Xt, Xo, Wq, Wk, Wv);
    proj_gemm<1><<<dim3((NSS + 127) / 128, D_ / 128, 3), 256>>>(Xt, Xo, Wq, Wk, Wv);
    temporal_attn_kernel<<<dim3(8, 8, 8), 256>>>(bq, bk, bv, out);
    others_attn_kernel<<<dim3(3, 8, 8), 256>>>(bq, bk, bv, out);
}

// round 2
// speedup vs baseline: 1.6027x; 1.6027x over previous
#include <cuda_runtime.h>
#include <mma.h>

using namespace nvcuda;

// ---------------- problem constants ----------------
constexpr int B_  = 8;
constexpr int L_  = 512;   // T-1
constexpr int M_  = 8;
constexpr int D_  = 512;
constexpr int DH_ = 64;
constexpr int O_  = 64;
constexpr int SS_ = 72;    // M + O

constexpr int NTT = B_ * L_ * M_;   // 32768 temporal rows
constexpr int NSS = B_ * SS_;       // 576 ss rows

constexpr long long SZ_TOUT = (long long)B_ * 513 * M_ * D_;       // 16,809,984
constexpr long long SZ_OOUT = (long long)B_ * O_ * D_;             // 262,144
constexpr long long SZ_TATT = (long long)B_ * 8 * L_ * M_ * SS_;   // 18,874,368
constexpr long long OFF_OOUT = SZ_TOUT;
constexpr long long OFF_TATT = OFF_OOUT + SZ_OOUT;
constexpr long long OFF_OATT = OFF_TATT + SZ_TATT;

// ---------------- scratch (static device globals; no allocs) ----------------
__device__ float g_tt[3][(size_t)NTT * D_];   // Qtt, Ktt, Vtt (no bias)
__device__ float g_ss[3][(size_t)NSS * D_];   // Qss, Kss, Vss (no bias); Kts/Vts = rows 8..71

__device__ __forceinline__ float to_tf32(float x) {
    asm("cvt.rna.tf32.f32 %0, %0;" : "+f"(x));
    return x;
}

// ============================================================================
// Projection GEMM v2: C[r,n] = sum_d X[r,d] * W[n,d]  (bias deferred)
// tf32 WMMA, BM=256 BN=128 BK=32, 512 threads / 16 warps (4x4), warp = 64x32.
// tf32 conversion done ONCE at smem staging.
// ============================================================================
constexpr int P_BM = 256, P_BN = 128, P_BK = 32, P_LD = P_BK + 4;
constexpr int SMEM_PROJ = (P_BM + P_BN) * P_LD * 4;   // 55296 bytes

template<int MODE>
__global__ __launch_bounds__(512) void proj_gemm(
    const float* __restrict__ Xt, const float* __restrict__ Xo,
    const float* __restrict__ Wq, const float* __restrict__ Wk,
    const float* __restrict__ Wv)
{
    extern __shared__ float sm[];
    float* As = sm;                    // [P_BM][P_LD]
    float* Bs = sm + P_BM * P_LD;      // [P_BN][P_LD]

    const int tid  = threadIdx.x;
    const int warp = tid >> 5;
    const int wr   = warp >> 2;   // 0..3 (64-row strips)
    const int wc   = warp & 3;    // 0..3 (32-col strips)
    const int tm   = blockIdx.x;
    const int tn   = blockIdx.y;
    const int mat  = blockIdx.z;

    const float* W   = (mat == 0) ? Wq : ((mat == 1) ? Wk : Wv);
    float*       Out = (MODE == 0) ? g_tt[mat] : g_ss[mat];
    const int  Mrows = (MODE == 0) ? NTT : NSS;

    wmma::fragment<wmma::accumulator, 16, 16, 8, float> acc[4][2];
#pragma unroll
    for (int i = 0; i < 4; i++)
#pragma unroll
        for (int j = 0; j < 2; j++) wmma::fill_fragment(acc[i][j], 0.0f);

    for (int k0 = 0; k0 < D_; k0 += P_BK) {
        // ---- stage A (256x32) : 2048 float4 over 512 threads ----
#pragma unroll
        for (int i = 0; i < 4; i++) {
            int idx = tid + i * 512;
            int r   = idx >> 3;
            int c4  = (idx & 7) * 4;
            float4 v = make_float4(0.f, 0.f, 0.f, 0.f);
            int gr = tm * P_BM + r;
            if (MODE == 0) {
                const float* src = Xt + (size_t)(gr + ((gr >> 12) << 3) + 8) * D_;
                v = *reinterpret_cast<const float4*>(src + k0 + c4);
            } else if (gr < NSS) {
                int bb = gr / SS_;
                int jj = gr - bb * SS_;
                const float* src = (jj < M_) ? (Xt + (size_t)(bb * 4104 + jj) * D_)
                                             : (Xo + (size_t)(bb * O_ + jj - M_) * D_);
                v = *reinterpret_cast<const float4*>(src + k0 + c4);
            }
            v.x = to_tf32(v.x); v.y = to_tf32(v.y); v.z = to_tf32(v.z); v.w = to_tf32(v.w);
            *reinterpret_cast<float4*>(&As[r * P_LD + c4]) = v;
        }
        // ---- stage B (128x32) : 1024 float4 ----
#pragma unroll
        for (int i = 0; i < 2; i++) {
            int idx = tid + i * 512;
            int r   = idx >> 3;
            int c4  = (idx & 7) * 4;
            float4 w = *reinterpret_cast<const float4*>(W + (size_t)(tn * P_BN + r) * D_ + k0 + c4);
            w.x = to_tf32(w.x); w.y = to_tf32(w.y); w.z = to_tf32(w.z); w.w = to_tf32(w.w);
            *reinterpret_cast<float4*>(&Bs[r * P_LD + c4]) = w;
        }
        __syncthreads();

#pragma unroll
        for (int kk = 0; kk < P_BK; kk += 8) {
            wmma::fragment<wmma::matrix_a, 16, 16, 8, wmma::precision::tf32, wmma::row_major> af[4];
            wmma::fragment<wmma::matrix_b, 16, 16, 8, wmma::precision::tf32, wmma::col_major> bf[2];
#pragma unroll
            for (int i = 0; i < 4; i++)
                wmma::load_matrix_sync(af[i], &As[(wr * 64 + i * 16) * P_LD + kk], P_LD);
#pragma unroll
            for (int j = 0; j < 2; j++)
                wmma::load_matrix_sync(bf[j], &Bs[(wc * 32 + j * 16) * P_LD + kk], P_LD);
#pragma unroll
            for (int i = 0; i < 4; i++)
#pragma unroll
                for (int j = 0; j < 2; j++)
                    wmma::mma_sync(acc[i][j], af[i], bf[j], acc[i][j]);
        }
        __syncthreads();
    }

#pragma unroll
    for (int i = 0; i < 4; i++) {
        int row0 = tm * P_BM + wr * 64 + i * 16;
        if (row0 + 16 <= Mrows) {
#pragma unroll
            for (int j = 0; j < 2; j++)
                wmma::store_matrix_sync(Out + (size_t)row0 * D_ + tn * P_BN + wc * 32 + j * 16,
                                        acc[i][j], D_, wmma::mem_row_major);
        }
    }
}

// ============================================================================
// Temporal attention v2. Block = (b, h, chunk of 64 l). 256 threads.
// Processes 8 l's per iteration: 64x72 logits / 64x64 PV with 4x4 register
// tiles and float4 smem traffic.
// ============================================================================
constexpr int ST  = 68;   // stride for 64-wide smem arrays (float4 aligned)
constexpr int STS = 76;   // stride for 72-wide S/P array
constexpr int SMEM_ATT = (5 * 64 * ST + 64 * STS + 3 * 64) * 4;  // 107264 bytes

__global__ __launch_bounds__(256) void temporal_attn_kernel(
    const float* __restrict__ bq, const float* __restrict__ bk,
    const float* __restrict__ bv, float* __restrict__ out)
{
    extern __shared__ float sm[];
    float* Kts = sm;
    float* Vts = Kts + 64 * ST;
    float* Ql  = Vts + 64 * ST;
    float* Kl  = Ql  + 64 * ST;
    float* Vl  = Kl  + 64 * ST;
    float* P   = Vl  + 64 * ST;      // [64][STS]
    float* bqs = P   + 64 * STS;
    float* bks = bqs + 64;
    float* bvs = bks + 64;

    const int tid  = threadIdx.x;
    const int warp = tid >> 5;
    const int lane = tid & 31;
    const int b  = blockIdx.z, h = blockIdx.y;
    const int l0 = blockIdx.x * 64;
    const int cb = h * DH_;
    const int c4 = (tid & 15) * 4;   // column group this thread stages

    if (tid < 64) {
        bqs[tid] = bq[cb + tid];
        bks[tid] = bk[cb + tid];
        bvs[tid] = bv[cb + tid];
    }
    __syncthreads();

    const float4 bq4 = *reinterpret_cast<const float4*>(&bqs[c4]);
    const float4 bk4 = *reinterpret_cast<const float4*>(&bks[c4]);
    const float4 bv4 = *reinterpret_cast<const float4*>(&bvs[c4]);

    // ---- stage Kts/Vts (64x64) once ----
#pragma unroll
    for (int i = 0; i < 4; i++) {
        int idx = tid + i * 256;
        int o = idx >> 4;
        size_t srow = (size_t)(b * SS_ + 8 + o) * D_ + cb + c4;
        float4 kv = *reinterpret_cast<const float4*>(&g_ss[1][srow]);
        kv.x += bk4.x; kv.y += bk4.y; kv.z += bk4.z; kv.w += bk4.w;
        *reinterpret_cast<float4*>(&Kts[o * ST + c4]) = kv;
        float4 vv = *reinterpret_cast<const float4*>(&g_ss[2][srow]);
        vv.x += bv4.x; vv.y += bv4.y; vv.z += bv4.z; vv.w += bv4.w;
        *reinterpret_cast<float4*>(&Vts[o * ST + c4]) = vv;
    }
    __syncthreads();

    for (int li0 = 0; li0 < 64; li0 += 8) {
        const size_t rbase = (size_t)b * 4096 + (size_t)(l0 + li0) * 8;  // g_tt row base

        // ---- stage Ql/Kl/Vl (64x64 each) ----
#pragma unroll
        for (int i = 0; i < 4; i++) {
            int idx = tid + i * 256;
            int r = idx >> 4;
            size_t off = (rbase + r) * D_ + cb + c4;
            float4 q = *reinterpret_cast<const float4*>(&g_tt[0][off]);
            q.x += bq4.x; q.y += bq4.y; q.z += bq4.z; q.w += bq4.w;
            *reinterpret_cast<float4*>(&Ql[r * ST + c4]) = q;
            float4 k = *reinterpret_cast<const float4*>(&g_tt[1][off]);
            k.x += bk4.x; k.y += bk4.y; k.z += bk4.z; k.w += bk4.w;
            *reinterpret_cast<float4*>(&Kl[r * ST + c4]) = k;
            float4 v = *reinterpret_cast<const float4*>(&g_tt[2][off]);
            v.x += bv4.x; v.y += bv4.y; v.z += bv4.z; v.w += bv4.w;
            *reinterpret_cast<float4*>(&Vl[r * ST + c4]) = v;
        }
        __syncthreads();

        // ---- logits: S[r][k] = Q[r] . K(k),  4x4 register tiles ----
        {
            auto tile = [&](int rt, int kt) {
                const int r0 = rt * 4;
                const int li = r0 >> 3;
                const float* Krow[4];
                Krow[0] = (kt < 8) ? &Kl[(li * 8 + kt) * ST] : &Kts[(kt - 8) * ST];
                Krow[1] = &Kts[(kt + 10) * ST];
                Krow[2] = &Kts[(kt + 28) * ST];
                Krow[3] = &Kts[(kt + 46) * ST];
                const float* Q0 = &Ql[(r0 + 0) * ST];
                const float* Q1 = &Ql[(r0 + 1) * ST];
                const float* Q2 = &Ql[(r0 + 2) * ST];
                const float* Q3 = &Ql[(r0 + 3) * ST];
                float acc[4][4];
#pragma unroll
                for (int i = 0; i < 4; i++)
#pragma unroll
                    for (int j = 0; j < 4; j++) acc[i][j] = 0.f;
#pragma unroll
                for (int d = 0; d < 64; d += 4) {
                    float4 q0 = *reinterpret_cast<const float4*>(Q0 + d);
                    float4 q1 = *reinterpret_cast<const float4*>(Q1 + d);
                    float4 q2 = *reinterpret_cast<const float4*>(Q2 + d);
                    float4 q3 = *reinterpret_cast<const float4*>(Q3 + d);
#pragma unroll
                    for (int j = 0; j < 4; j++) {
                        float4 kk = *reinterpret_cast<const float4*>(Krow[j] + d);
                        acc[0][j] = fmaf(q0.x, kk.x, fmaf(q0.y, kk.y, fmaf(q0.z, kk.z, fmaf(q0.w, kk.w, acc[0][j]))));
                        acc[1][j] = fmaf(q1.x, kk.x, fmaf(q1.y, kk.y, fmaf(q1.z, kk.z, fmaf(q1.w, kk.w, acc[1][j]))));
                        acc[2][j] = fmaf(q2.x, kk.x, fmaf(q2.y, kk.y, fmaf(q2.z, kk.z, fmaf(q2.w, kk.w, acc[2][j]))));
                        acc[3][j] = fmaf(q3.x, kk.x, fmaf(q3.y, kk.y, fmaf(q3.z, kk.z, fmaf(q3.w, kk.w, acc[3][j]))));
                    }
                }
#pragma unroll
                for (int i = 0; i < 4; i++)
#pragma unroll
                    for (int j = 0; j < 4; j++)
                        P[(r0 + i) * STS + kt + 18 * j] = acc[i][j] * 0.125f;
            };
            tile(tid >> 4, tid & 15);              // k cols {0..15}+18j
            if (tid < 32) tile(tid >> 1, 16 + (tid & 1));  // k cols {16,17}+18j
        }
        __syncthreads();

        // ---- softmax: warp handles 8 rows; writes probs to gmem + P ----
        for (int i = 0; i < 8; i++) {
            int r = warp * 8 + i;
            float* Pr = &P[r * STS];
            float v0 = Pr[lane];
            float v1 = Pr[lane + 32];
            float v2 = (lane < 8) ? Pr[lane + 64] : -3.4e38f;
            float mx = fmaxf(fmaxf(v0, v1), v2);
#pragma unroll
            for (int s = 16; s; s >>= 1) mx = fmaxf(mx, __shfl_xor_sync(0xffffffffu, mx, s));
            float e0 = __expf(v0 - mx), e1 = __expf(v1 - mx);
            float e2 = (lane < 8) ? __expf(v2 - mx) : 0.f;
            float smv = e0 + e1 + e2;
#pragma unroll
            for (int s = 16; s; s >>= 1) smv += __shfl_xor_sync(0xffffffffu, smv, s);
            float inv = 1.0f / smv;
            float p0 = e0 * inv, p1 = e1 * inv;
            size_t abase = OFF_TATT + ((size_t)(b * 8 + h) * 4096 + (size_t)(l0 + li0) * 8 + r) * 72;
            Pr[lane] = p0;       out[abase + lane]      = p0;
            Pr[lane + 32] = p1;  out[abase + lane + 32] = p1;
            if (lane < 8) {
                float p2 = e2 * inv;
                Pr[lane + 64] = p2;
                out[abase + lane + 64] = p2;
            }
        }
        __syncthreads();

        // ---- PV: out(64x64), 4x4 register tiles ----
        {
            const int rt = tid >> 4, dt = tid & 15;
            const int r0 = rt * 4, d0 = dt * 4;
            const int li = r0 >> 3;
            float4 o0 = make_float4(0.f, 0.f, 0.f, 0.f);
            float4 o1 = o0, o2 = o0, o3 = o0;
#pragma unroll
            for (int nc = 0; nc < 18; nc++) {
                int n0 = nc * 4;
                const float* Vb = (nc < 2) ? &Vl[(li * 8 + n0) * ST] : &Vts[(n0 - 8) * ST];
                float4 p0 = *reinterpret_cast<const float4*>(&P[(r0 + 0) * STS + n0]);
                float4 p1 = *reinterpret_cast<const float4*>(&P[(r0 + 1) * STS + n0]);
                float4 p2 = *reinterpret_cast<const float4*>(&P[(r0 + 2) * STS + n0]);
                float4 p3 = *reinterpret_cast<const float4*>(&P[(r0 + 3) * STS + n0]);
#define PVSTEP(J, PA, PB, PC, PD)                                                        \
                {                                                                        \
                    float4 v = *reinterpret_cast<const float4*>(Vb + (J) * ST + d0);     \
                    o0.x = fmaf(PA, v.x, o0.x); o0.y = fmaf(PA, v.y, o0.y);              \
                    o0.z = fmaf(PA, v.z, o0.z); o0.w = fmaf(PA, v.w, o0.w);              \
                    o1.x = fmaf(PB, v.x, o1.x); o1.y = fmaf(PB, v.y, o1.y);              \
                    o1.z = fmaf(PB, v.z, o1.z); o1.w = fmaf(PB, v.w, o1.w);              \
                    o2.x = fmaf(PC, v.x, o2.x); o2.y = fmaf(PC, v.y, o2.y);              \
                    o2.z = fmaf(PC, v.z, o2.z); o2.w = fmaf(PC, v.w, o2.w);              \
                    o3.x = fmaf(PD, v.x, o3.x); o3.y = fmaf(PD, v.y, o3.y);              \
                    o3.z = fmaf(PD, v.z, o3.z); o3.w = fmaf(PD, v.w, o3.w);              \
                }
                PVSTEP(0, p0.x, p1.x, p2.x, p3.x)
                PVSTEP(1, p0.y, p1.y, p2.y, p3.y)
                PVSTEP(2, p0.z, p1.z, p2.z, p3.z)
                PVSTEP(3, p0.w, p1.w, p2.w, p3.w)
#undef PVSTEP
            }
            const size_t orow = (size_t)(b * 4104 + 8 + (l0 + li0) * 8);
            *reinterpret_cast<float4*>(&out[(orow + r0 + 0) * D_ + cb + d0]) = o0;
            *reinterpret_cast<float4*>(&out[(orow + r0 + 1) * D_ + cb + d0]) = o1;
            *reinterpret_cast<float4*>(&out[(orow + r0 + 2) * D_ + cb + d0]) = o2;
            *reinterpret_cast<float4*>(&out[(orow + r0 + 3) * D_ + cb + d0]) = o3;
        }
        __syncthreads();
    }
}

// ============================================================================
// Others attention (unchanged; small).
// ============================================================================
__global__ void others_attn_kernel(const float* __restrict__ bq, const float* __restrict__ bk,
                                   const float* __restrict__ bv, float* __restrict__ out)
{
    __shared__ float Qc[24][65];
    __shared__ float KV[72][65];
    __shared__ float S[24][73];
    __shared__ float bq_s[64], bk_s[64], bv_s[64];

    const int tid = threadIdx.x;
    const int m0 = blockIdx.x * 24;
    const int h = blockIdx.y, b = blockIdx.z;
    const int cb = h * DH_;

    if (tid < 64) {
        bq_s[tid] = bq[cb + tid];
        bk_s[tid] = bk[cb + tid];
        bv_s[tid] = bv[cb + tid];
    }
    __syncthreads();

    for (int idx = tid; idx < 72 * 64; idx += 256) {
        int n = idx >> 6, d = idx & 63;
        KV[n][d] = g_ss[1][(size_t)(b * SS_ + n) * D_ + cb + d] + bk_s[d];
    }
    for (int idx = tid; idx < 24 * 64; idx += 256) {
        int i = idx >> 6, d = idx & 63;
        Qc[i][d] = g_ss[0][(size_t)(b * SS_ + m0 + i) * D_ + cb + d] + bq_s[d];
    }
    __syncthreads();

    for (int e = tid; e < 24 * 72; e += 256) {
        int i = e / 72, n = e - i * 72;
        float acc = 0.f;
#pragma unroll
        for (int d = 0; d < 64; d++) acc = fmaf(Qc[i][d], KV[n][d], acc);
        S[i][n] = acc * 0.125f;
    }
    __syncthreads();

    {
        int w = tid >> 5, lane = tid & 31;
        for (int i = w; i < 24; i += 8) {
            float v0 = S[i][lane];
            float v1 = S[i][lane + 32];
            float v2 = (lane < 8) ? S[i][lane + 64] : -3.4e38f;
            float mx = fmaxf(fmaxf(v0, v1), v2);
#pragma unroll
            for (int s = 16; s; s >>= 1) mx = fmaxf(mx, __shfl_xor_sync(0xffffffffu, mx, s));
            float e0 = __expf(v0 - mx), e1 = __expf(v1 - mx);
            float e2 = (lane < 8) ? __expf(v2 - mx) : 0.f;
            float smv = e0 + e1 + e2;
#pragma unroll
            for (int s = 16; s; s >>= 1) smv += __shfl_xor_sync(0xffffffffu, smv, s);
            float inv = 1.0f / smv;
            size_t abase = OFF_OATT + ((size_t)(b * 8 + h) * 72 + (m0 + i)) * 72;
            float p0 = e0 * inv, p1 = e1 * inv;
            S[i][lane] = p0;       out[abase + lane]      = p0;
            S[i][lane + 32] = p1;  out[abase + lane + 32] = p1;
            if (lane < 8) {
                float p2 = e2 * inv;
                S[i][lane + 64] = p2;
                out[abase + lane + 64] = p2;
            }
        }
    }
    __syncthreads();

    for (int idx = tid; idx < 72 * 64; idx += 256) {
        int n = idx >> 6, d = idx & 63;
        KV[n][d] = g_ss[2][(size_t)(b * SS_ + n) * D_ + cb + d] + bv_s[d];
    }
    __syncthreads();

    for (int e = tid; e < 24 * 64; e += 256) {
        int i = e >> 6, d = e & 63;
        float acc = 0.f;
#pragma unroll
        for (int n = 0; n < 72; n++) acc = fmaf(S[i][n], KV[n][d], acc);
        int ng = m0 + i;
        int p = h * 4608 + ng * 64 + d;
        int j = p >> 9;
        int c = p & 511;
        if (j < 8)
            out[(size_t)(b * 4104 + j) * D_ + c] = acc;
        else
            out[OFF_OOUT + (size_t)(b * 64 + (j - 8)) * D_ + c] = acc;
    }
}

// ============================================================================
extern "C" void kernel_launch(void* const* d_in, const int* in_sizes, int n_in,
                              void* d_out, int out_size)
{
    const float* Xt = (const float*)d_in[0];
    const float* Xo = (const float*)d_in[1];
    const float* Wq = (const float*)d_in[2];
    const float* bq = (const float*)d_in[3];
    const float* Wk = (const float*)d_in[4];
    const float* bk = (const float*)d_in[5];
    const float* Wv = (const float*)d_in[6];
    const float* bv = (const float*)d_in[7];
    float* out = (float*)d_out;

    cudaFuncSetAttribute((const void*)proj_gemm<0>, cudaFuncAttributeMaxDynamicSharedMemorySize, SMEM_PROJ);
    cudaFuncSetAttribute((const void*)proj_gemm<1>, cudaFuncAttributeMaxDynamicSharedMemorySize, SMEM_PROJ);
    cudaFuncSetAttribute((const void*)temporal_attn_kernel, cudaFuncAttributeMaxDynamicSharedMemorySize, SMEM_ATT);

    proj_gemm<0><<<dim3(NTT / P_BM, D_ / P_BN, 3), 512, SMEM_PROJ>>>(Xt, Xo, Wq, Wk, Wv);
    proj_gemm<1><<<dim3((NSS + P_BM - 1) / P_BM, D_ / P_BN, 3), 512, SMEM_PROJ>>>(Xt, Xo, Wq, Wk, Wv);
    temporal_attn_kernel<<<dim3(8, 8, 8), 256, SMEM_ATT>>>(bq, bk, bv, out);
    others_attn_kernel<<<dim3(3, 8, 8), 256>>>(bq, bk, bv, out);
}